// round 14
// baseline (speedup 1.0000x reference)
#include <cuda_runtime.h>
#include <cuda_fp16.h>
#include <cstdint>

#define NTOK 8192
#define CIN 512
#define DK 64
#define BM 64            // queries per CTA (attn)
#define BN 64            // keys per iteration
#define ITERS (NTOK / BN)
#define PCOLS 640

// ---------------- static scratch (fp16 operands) ----------------
__device__ __align__(16) __half g_qh[2][NTOK * DK];
__device__ __align__(16) __half g_ql[2][NTOK * DK];
__device__ __align__(16) __half g_kh[2][NTOK * DK];
__device__ __align__(16) __half g_kl[2][NTOK * DK];
__device__ __align__(16) __half g_vh[2][(size_t)NTOK * CIN];

// ---------------- PTX helpers (base ISA only) ----------------
__device__ __forceinline__ uint32_t smem_u32(const void* p) {
    uint32_t a;
    asm("{ .reg .u64 t; cvta.to.shared.u64 t, %1; cvt.u32.u64 %0, t; }" : "=r"(a) : "l"(p));
    return a;
}
__device__ __forceinline__ void mma16816(float* c, const uint32_t* a, uint32_t b0, uint32_t b1) {
    asm volatile(
        "mma.sync.aligned.m16n8k16.row.col.f32.f16.f16.f32 "
        "{%0,%1,%2,%3}, {%4,%5,%6,%7}, {%8,%9}, {%0,%1,%2,%3};"
        : "+f"(c[0]), "+f"(c[1]), "+f"(c[2]), "+f"(c[3])
        : "r"(a[0]), "r"(a[1]), "r"(a[2]), "r"(a[3]), "r"(b0), "r"(b1));
}
__device__ __forceinline__ void ldsm4(uint32_t* d, uint32_t addr) {
    asm volatile("ldmatrix.sync.aligned.m8n8.x4.shared.b16 {%0,%1,%2,%3}, [%4];"
                 : "=r"(d[0]), "=r"(d[1]), "=r"(d[2]), "=r"(d[3]) : "r"(addr));
}
__device__ __forceinline__ void ldsm4t(uint32_t* d, uint32_t addr) {
    asm volatile("ldmatrix.sync.aligned.m8n8.x4.trans.shared.b16 {%0,%1,%2,%3}, [%4];"
                 : "=r"(d[0]), "=r"(d[1]), "=r"(d[2]), "=r"(d[3]) : "r"(addr));
}
#define CP16(dst, src)  asm volatile("cp.async.cg.shared.global [%0], [%1], 16;" :: "r"(dst), "l"(src))
#define CPCOMMIT()      asm volatile("cp.async.commit_group;" ::: "memory")
#define CPWAIT0()       asm volatile("cp.async.wait_group 0;" ::: "memory")

// ---------------------------------------------------------------------------
// Kernel 1: HMMA QKV projection. V-CTAs use 2-term hi/lo (drop al*wh).
// ---------------------------------------------------------------------------
__global__ __launch_bounds__(256, 2)
void proj_kernel(const float* __restrict__ im1, const float* __restrict__ im2,
                 const float* __restrict__ Wq, const float* __restrict__ Wk,
                 const float* __restrict__ Wv) {
    const int img = blockIdx.z;
    const float* __restrict__ A = img ? im2 : im1;
    const int rowBase = blockIdx.x * 128;
    const int colBase = blockIdx.y * 64;
    const bool useAl = (colBase < 128);   // Q/K need full 3-term

    __shared__ __align__(16) __half Ah[128 * 32];
    __shared__ __align__(16) __half Al[128 * 32];
    __shared__ __align__(16) __half Wh[32 * 64];
    __shared__ __align__(16) __half Wl[32 * 64];

    const int tid = threadIdx.x, warp = tid >> 5, lane = tid & 31;
    const int wr = warp & 3, wc = warp >> 2;
    const int l7 = lane & 7, l8 = (lane >> 3) & 1, l16 = lane >> 4;
    const int lq = lane >> 2, lc = lane & 3;
    const uint32_t sAh = smem_u32(Ah), sAl = smem_u32(Al);
    const uint32_t sWh = smem_u32(Wh), sWl = smem_u32(Wl);

    float o[2][4][4] = {};
    float4 aR[4];
    float4 wR[2];

    auto loadA = [&](int kt) {
        #pragma unroll
        for (int i = 0; i < 4; i++) {
            int idx = tid + i * 256;
            int r = idx >> 3, c4 = idx & 7;
            aR[i] = *(const float4*)(A + (size_t)(rowBase + r) * CIN + kt * 32 + c4 * 4);
        }
    };
    auto loadW = [&](int kt) {
        #pragma unroll
        for (int i = 0; i < 2; i++) {
            int idx = tid + i * 256;
            int r = idx >> 4, c4 = idx & 15;
            int krow = kt * 32 + r;
            int c = colBase + c4 * 4;
            const float* src;
            if (c < 64)       src = Wq + krow * DK + c;
            else if (c < 128) src = Wk + krow * DK + (c - 64);
            else              src = Wv + krow * CIN + (c - 128);
            wR[i] = *(const float4*)src;
        }
    };

    loadA(0); loadW(0);

    for (int kt = 0; kt < 16; kt++) {
        #pragma unroll
        for (int i = 0; i < 4; i++) {
            int idx = tid + i * 256;
            int r = idx >> 3, c4 = idx & 7;
            uint32_t off = (uint32_t)(r * 64 + (((c4 >> 1) ^ (r & 3)) * 16) + (c4 & 1) * 8);
            float4 v = aR[i];
            __half h0 = __float2half_rn(v.x), h1 = __float2half_rn(v.y);
            __half h2 = __float2half_rn(v.z), h3 = __float2half_rn(v.w);
            __half2 H0 = __halves2half2(h0, h1), H1 = __halves2half2(h2, h3);
            __half2 L0 = __halves2half2(__float2half_rn(v.x - __half2float(h0)),
                                        __float2half_rn(v.y - __half2float(h1)));
            __half2 L1 = __halves2half2(__float2half_rn(v.z - __half2float(h2)),
                                        __float2half_rn(v.w - __half2float(h3)));
            *(uint2*)((char*)Ah + off) = make_uint2(*(uint32_t*)&H0, *(uint32_t*)&H1);
            *(uint2*)((char*)Al + off) = make_uint2(*(uint32_t*)&L0, *(uint32_t*)&L1);
        }
        #pragma unroll
        for (int i = 0; i < 2; i++) {
            int idx = tid + i * 256;
            int r = idx >> 4, c4 = idx & 15;
            uint32_t off = (uint32_t)(r * 128 + (((c4 >> 1) ^ (r & 7)) * 16) + (c4 & 1) * 8);
            float4 v = wR[i];
            __half h0 = __float2half_rn(v.x), h1 = __float2half_rn(v.y);
            __half h2 = __float2half_rn(v.z), h3 = __float2half_rn(v.w);
            __half2 H0 = __halves2half2(h0, h1), H1 = __halves2half2(h2, h3);
            __half2 L0 = __halves2half2(__float2half_rn(v.x - __half2float(h0)),
                                        __float2half_rn(v.y - __half2float(h1)));
            __half2 L1 = __halves2half2(__float2half_rn(v.z - __half2float(h2)),
                                        __float2half_rn(v.w - __half2float(h3)));
            *(uint2*)((char*)Wh + off) = make_uint2(*(uint32_t*)&H0, *(uint32_t*)&H1);
            *(uint2*)((char*)Wl + off) = make_uint2(*(uint32_t*)&L0, *(uint32_t*)&L1);
        }
        __syncthreads();

        if (kt + 1 < 16) { loadA(kt + 1); loadW(kt + 1); }

        #pragma unroll
        for (int ks = 0; ks < 2; ks++) {
            uint32_t wh[2][4], wl[2][4];
            #pragma unroll
            for (int nt = 0; nt < 2; nt++) {
                int rr = ks * 16 + l7 + l8 * 8;
                uint32_t chunk = (uint32_t)((wc * 4 + nt * 2 + l16) ^ (rr & 7));
                ldsm4t(wh[nt], sWh + rr * 128 + chunk * 16);
                ldsm4t(wl[nt], sWl + rr * 128 + chunk * 16);
            }
            #pragma unroll
            for (int rt = 0; rt < 2; rt++) {
                int ar = wr * 32 + rt * 16 + l7 + l8 * 8;
                uint32_t ach = (uint32_t)((ks * 2 + l16) ^ (ar & 3));
                uint32_t ah[4], al[4];
                ldsm4(ah, sAh + ar * 64 + ach * 16);
                ldsm4(al, sAl + ar * 64 + ach * 16);
                #pragma unroll
                for (int nt = 0; nt < 2; nt++) {
                    mma16816(o[rt][nt * 2 + 0], ah, wh[nt][0], wh[nt][1]);
                    mma16816(o[rt][nt * 2 + 1], ah, wh[nt][2], wh[nt][3]);
                    mma16816(o[rt][nt * 2 + 0], ah, wl[nt][0], wl[nt][1]);
                    mma16816(o[rt][nt * 2 + 1], ah, wl[nt][2], wl[nt][3]);
                    if (useAl) {
                        mma16816(o[rt][nt * 2 + 0], al, wh[nt][0], wh[nt][1]);
                        mma16816(o[rt][nt * 2 + 1], al, wh[nt][2], wh[nt][3]);
                    }
                }
            }
        }
        __syncthreads();
    }

    #pragma unroll
    for (int rt = 0; rt < 2; rt++) {
        #pragma unroll
        for (int n = 0; n < 4; n++) {
            int rowA = rowBase + wr * 32 + rt * 16 + lq;
            int rowB = rowA + 8;
            int cA = wc * 32 + n * 8 + lc * 2;
            float v0 = o[rt][n][0], v1 = o[rt][n][1];
            float v2 = o[rt][n][2], v3 = o[rt][n][3];
            if (colBase == 0) {
                __half h0 = __float2half_rn(v0), h1 = __float2half_rn(v1);
                __half h2 = __float2half_rn(v2), h3 = __float2half_rn(v3);
                *(__half2*)&g_qh[img][rowA * DK + cA] = __halves2half2(h0, h1);
                *(__half2*)&g_qh[img][rowB * DK + cA] = __halves2half2(h2, h3);
                *(__half2*)&g_ql[img][rowA * DK + cA] =
                    __halves2half2(__float2half_rn(v0 - __half2float(h0)),
                                   __float2half_rn(v1 - __half2float(h1)));
                *(__half2*)&g_ql[img][rowB * DK + cA] =
                    __halves2half2(__float2half_rn(v2 - __half2float(h2)),
                                   __float2half_rn(v3 - __half2float(h3)));
            } else if (colBase == 64) {
                __half h0 = __float2half_rn(v0), h1 = __float2half_rn(v1);
                __half h2 = __float2half_rn(v2), h3 = __float2half_rn(v3);
                *(__half2*)&g_kh[img][rowA * DK + cA] = __halves2half2(h0, h1);
                *(__half2*)&g_kh[img][rowB * DK + cA] = __halves2half2(h2, h3);
                *(__half2*)&g_kl[img][rowA * DK + cA] =
                    __halves2half2(__float2half_rn(v0 - __half2float(h0)),
                                   __float2half_rn(v1 - __half2float(h1)));
                *(__half2*)&g_kl[img][rowB * DK + cA] =
                    __halves2half2(__float2half_rn(v2 - __half2float(h2)),
                                   __float2half_rn(v3 - __half2float(h3)));
            } else {
                int cv = colBase - 128 + cA;
                *(__half2*)&g_vh[img][(size_t)rowA * CIN + cv] =
                    __halves2half2(__float2half_rn(v0), __float2half_rn(v1));
                *(__half2*)&g_vh[img][(size_t)rowB * CIN + cv] =
                    __halves2half2(__float2half_rn(v2), __float2half_rn(v3));
            }
        }
    }
}

// ---------------- attn smem layout (BM=64, R11 structure) ----------------
#define IX_MROW(cur, row) ((cur) * 64 + (row))
#define IX_CORR(row)      (128 + (row))
#define IX_PMAX(g, row)   (192 + (g) * 64 + (row))
#define IX_PSUM(g, row)   (448 + (g) * 64 + (row))
#define SM_QH    3072
#define SM_QL    (SM_QH + 8192)
#define SM_KH(b) (19456 + (b) * 16384)
#define SM_KL(b) (27648 + (b) * 16384)
#define SM_V(b)  (52224 + (b) * 65536)
#define SM_P(b)  (183296 + (b) * 16384)
#define SM_TOTAL 216064

__device__ __forceinline__ void load_kv(uint32_t SB, const __half* Kh, const __half* Kl,
                                        const __half* Vh, int kb, int buf, int tid) {
    int r = tid >> 3, c = tid & 7;
    uint32_t sw = (uint32_t)((c ^ (r & 7)) * 16);
    CP16(SB + SM_KH(buf) + r * 128 + sw, Kh + (size_t)(kb + r) * DK + c * 8);
    CP16(SB + SM_KL(buf) + r * 128 + sw, Kl + (size_t)(kb + r) * DK + c * 8);
    #pragma unroll
    for (int i = 0; i < 8; i++) {
        int idx = tid + i * 512;
        int vr = idx >> 6, vc = idx & 63;
        CP16(SB + SM_V(buf) + vr * 1024 + (uint32_t)((vc ^ (vr & 7)) * 16),
             Vh + (size_t)(kb + vr) * CIN + vc * 8);
    }
}

// ---------------------------------------------------------------------------
// Kernel 2: HMMA flash attention, deferred PV, Q fragments hoisted to regs.
// grid (128 qblocks, 2 sides), 512 threads, 2 barriers/iter.
// ---------------------------------------------------------------------------
__global__ __launch_bounds__(512, 1)
void attn_kernel(const float* __restrict__ im1, const float* __restrict__ im2,
                 float* __restrict__ out_all) {
    extern __shared__ char smem[];
    const uint32_t SB = smem_u32(smem);
    float* const stats = (float*)smem;

    const int tid  = threadIdx.x;
    const int warp = tid >> 5;
    const int lane = tid & 31;
    const int side  = blockIdx.y;
    const int qBase = blockIdx.x * BM;

    const __half* __restrict__ Qh = g_qh[side ^ 1];
    const __half* __restrict__ Ql = g_ql[side ^ 1];
    const __half* __restrict__ Kh = g_kh[side];
    const __half* __restrict__ Kl = g_kl[side];
    const __half* __restrict__ Vh = g_vh[side];
    const float* __restrict__ resid = side ? im2 : im1;
    float* __restrict__ out = out_all + (size_t)side * NTOK * CIN;

    const int rg = warp & 3;
    const int kg = warp >> 2;
    const int rows0 = rg * 16;
    const int key0  = kg * 16;
    const int chW   = warp * 32;

    const int l7  = lane & 7;
    const int l8  = (lane >> 3) & 1;
    const int l16 = lane >> 4;
    const int lq  = lane >> 2;
    const int lc  = lane & 3;
    const int row_a = rows0 + lq;
    const int row_b = row_a + 8;

    auto frag128 = [&](uint32_t base, int row0, int ks) -> uint32_t {
        int r  = row0 + l7 + l8 * 8;
        int ch = ks * 2 + l16;
        return SB + base + r * 128 + (uint32_t)(((ch ^ (r & 7)) & 7) * 16);
    };
    auto fragV = [&](int buf, int k0, int n0) -> uint32_t {
        int r  = k0 + l7 + l8 * 8;
        int ch = (n0 >> 3) + l16;
        return SB + SM_V(buf) + r * 1024 + (uint32_t)((ch ^ (r & 7)) * 16);
    };

    // ---- prologue: Q + K/V(0) ----
    if (tid < 64) stats[IX_MROW(0, tid)] = -1e30f;
    {
        int r = tid >> 3, c = tid & 7;
        uint32_t sw = (uint32_t)((c ^ (r & 7)) * 16);
        CP16(SB + SM_QH + r * 128 + sw, Qh + (size_t)(qBase + r) * DK + c * 8);
        CP16(SB + SM_QL + r * 128 + sw, Ql + (size_t)(qBase + r) * DK + c * 8);
        load_kv(SB, Kh, Kl, Vh, 0, 0, tid);
        CPCOMMIT();
    }
    CPWAIT0();
    __syncthreads();

    // ---- hoist Q fragments (loop-invariant): 32 regs ----
    uint32_t qfh[4][4], qfl[4][4];
    #pragma unroll
    for (int ks = 0; ks < 4; ks++) {
        ldsm4(qfh[ks], frag128(SM_QH, rows0, ks));
        ldsm4(qfl[ks], frag128(SM_QL, rows0, ks));
    }

    float o[4][4][4];
    #pragma unroll
    for (int rt = 0; rt < 4; rt++)
        #pragma unroll
        for (int n = 0; n < 4; n++)
            #pragma unroll
            for (int i = 0; i < 4; i++) o[rt][n][i] = 0.f;
    float l_reg = 0.f, corr_prev = 0.f;   // owner state (tid < 64)

    for (int it = 0; it < ITERS; it++) {
        const int b   = it & 1;
        const int bp  = b ^ 1;
        const int cur = it & 1, nxt = cur ^ 1;

        // ---------- Phase 1: QK(it) (Q from registers) ----------
        float s[2][4];
        #pragma unroll
        for (int t = 0; t < 2; t++)
            #pragma unroll
            for (int i = 0; i < 4; i++) s[t][i] = 0.f;
        #pragma unroll
        for (int ks = 0; ks < 4; ks++) {
            uint32_t bkh[4], bkl[4];
            ldsm4(bkh, frag128(SM_KH(b), key0, ks));
            ldsm4(bkl, frag128(SM_KL(b), key0, ks));
            mma16816(s[0], qfh[ks], bkh[0], bkh[2]);
            mma16816(s[1], qfh[ks], bkh[1], bkh[3]);
            mma16816(s[0], qfh[ks], bkl[0], bkl[2]);
            mma16816(s[1], qfh[ks], bkl[1], bkl[3]);
            mma16816(s[0], qfl[ks], bkh[0], bkh[2]);
            mma16816(s[1], qfl[ks], bkh[1], bkh[3]);
        }

        // ---------- Phase 2: deferred PV(it-1) ----------
        if (it > 0) {
            if (tid < 64) {
                float ls = 0.f;
                #pragma unroll
                for (int g = 0; g < 4; g++) ls += stats[IX_PSUM(g, tid)];
                l_reg = l_reg * corr_prev + ls;
            }
            {
                float cr[4][2];
                bool allone = true;
                #pragma unroll
                for (int rt = 0; rt < 4; rt++) {
                    cr[rt][0] = stats[IX_CORR(rt * 16 + lq)];
                    cr[rt][1] = stats[IX_CORR(rt * 16 + lq + 8)];
                    allone = allone && (cr[rt][0] == 1.0f) && (cr[rt][1] == 1.0f);
                }
                if (!__all_sync(0xffffffffu, allone)) {
                    #pragma unroll
                    for (int rt = 0; rt < 4; rt++)
                        #pragma unroll
                        for (int n = 0; n < 4; n++) {
                            o[rt][n][0] *= cr[rt][0]; o[rt][n][1] *= cr[rt][0];
                            o[rt][n][2] *= cr[rt][1]; o[rt][n][3] *= cr[rt][1];
                        }
                }
            }
            #pragma unroll
            for (int ks = 0; ks < 4; ks++) {
                uint32_t vf[2][4];
                ldsm4t(vf[0], fragV(bp, ks * 16, chW + 0));
                ldsm4t(vf[1], fragV(bp, ks * 16, chW + 16));
                #pragma unroll
                for (int rt = 0; rt < 4; rt++) {
                    uint32_t ap[4];
                    ldsm4(ap, frag128(SM_P(bp), rt * 16, ks));
                    mma16816(o[rt][0], ap, vf[0][0], vf[0][1]);
                    mma16816(o[rt][1], ap, vf[0][2], vf[0][3]);
                    mma16816(o[rt][2], ap, vf[1][0], vf[1][1]);
                    mma16816(o[rt][3], ap, vf[1][2], vf[1][3]);
                }
            }
        }

        // ---------- Phase 3a: publish partial maxima ----------
        float ma = fmaxf(fmaxf(s[0][0], s[0][1]), fmaxf(s[1][0], s[1][1]));
        float mb = fmaxf(fmaxf(s[0][2], s[0][3]), fmaxf(s[1][2], s[1][3]));
        ma = fmaxf(ma, __shfl_xor_sync(0xffffffffu, ma, 1));
        ma = fmaxf(ma, __shfl_xor_sync(0xffffffffu, ma, 2));
        mb = fmaxf(mb, __shfl_xor_sync(0xffffffffu, mb, 1));
        mb = fmaxf(mb, __shfl_xor_sync(0xffffffffu, mb, 2));
        if (lc == 0) {
            stats[IX_PMAX(kg, row_a)] = ma;
            stats[IX_PMAX(kg, row_b)] = mb;
        }
        __syncthreads();                                   // barrier #1

        // ---------- Phase 3b: prefetch K/V(it+1) into freed buffer ----------
        if (it + 1 < ITERS) load_kv(SB, Kh, Kl, Vh, (it + 1) * BN, bp, tid);
        CPCOMMIT();

        // ---------- Phase 3c: combine, exp, write P(it), psums ----------
        if (tid < 64) {
            float mo = stats[IX_MROW(cur, tid)], mn = mo;
            #pragma unroll
            for (int g = 0; g < 4; g++) mn = fmaxf(mn, stats[IX_PMAX(g, tid)]);
            corr_prev = __expf(mo - mn);
            stats[IX_MROW(nxt, tid)] = mn;
            stats[IX_CORR(tid)] = corr_prev;
        }
        {
            float mA = stats[IX_MROW(cur, row_a)];
            float mB = stats[IX_MROW(cur, row_b)];
            #pragma unroll
            for (int g = 0; g < 4; g++) {
                mA = fmaxf(mA, stats[IX_PMAX(g, row_a)]);
                mB = fmaxf(mB, stats[IX_PMAX(g, row_b)]);
            }
            float la = 0.f, lb = 0.f;
            #pragma unroll
            for (int t = 0; t < 2; t++) {
                float p0 = __expf(s[t][0] - mA);
                float p1 = __expf(s[t][1] - mA);
                float p2 = __expf(s[t][2] - mB);
                float p3 = __expf(s[t][3] - mB);
                la += p0 + p1;
                lb += p2 + p3;
                __half2 hA = __floats2half2_rn(p0, p1);
                __half2 hB = __floats2half2_rn(p2, p3);
                int ch = kg * 2 + t;
                *(uint32_t*)(smem + SM_P(b) + row_a * 128 + ((ch ^ (row_a & 7)) * 16) + lc * 4) =
                    *(uint32_t*)&hA;
                *(uint32_t*)(smem + SM_P(b) + row_b * 128 + ((ch ^ (row_b & 7)) * 16) + lc * 4) =
                    *(uint32_t*)&hB;
            }
            la += __shfl_xor_sync(0xffffffffu, la, 1);
            la += __shfl_xor_sync(0xffffffffu, la, 2);
            lb += __shfl_xor_sync(0xffffffffu, lb, 1);
            lb += __shfl_xor_sync(0xffffffffu, lb, 2);
            if (lc == 0) {
                stats[IX_PSUM(kg, row_a)] = la;
                stats[IX_PSUM(kg, row_b)] = lb;
            }
        }
        CPWAIT0();
        __syncthreads();                                   // barrier #2
    }

    // ---------- epilogue: final PV(ITERS-1) ----------
    {
        const int bl = (ITERS - 1) & 1;
        if (tid < 64) {
            float ls = 0.f;
            #pragma unroll
            for (int g = 0; g < 4; g++) ls += stats[IX_PSUM(g, tid)];
            l_reg = l_reg * corr_prev + ls;
        }
        {
            float cr[4][2];
            bool allone = true;
            #pragma unroll
            for (int rt = 0; rt < 4; rt++) {
                cr[rt][0] = stats[IX_CORR(rt * 16 + lq)];
                cr[rt][1] = stats[IX_CORR(rt * 16 + lq + 8)];
                allone = allone && (cr[rt][0] == 1.0f) && (cr[rt][1] == 1.0f);
            }
            if (!__all_sync(0xffffffffu, allone)) {
                #pragma unroll
                for (int rt = 0; rt < 4; rt++)
                    #pragma unroll
                    for (int n = 0; n < 4; n++) {
                        o[rt][n][0] *= cr[rt][0]; o[rt][n][1] *= cr[rt][0];
                        o[rt][n][2] *= cr[rt][1]; o[rt][n][3] *= cr[rt][1];
                    }
            }
        }
        #pragma unroll
        for (int ks = 0; ks < 4; ks++) {
            uint32_t vf[2][4];
            ldsm4t(vf[0], fragV(bl, ks * 16, chW + 0));
            ldsm4t(vf[1], fragV(bl, ks * 16, chW + 16));
            #pragma unroll
            for (int rt = 0; rt < 4; rt++) {
                uint32_t ap[4];
                ldsm4(ap, frag128(SM_P(bl), rt * 16, ks));
                mma16816(o[rt][0], ap, vf[0][0], vf[0][1]);
                mma16816(o[rt][1], ap, vf[0][2], vf[0][3]);
                mma16816(o[rt][2], ap, vf[1][0], vf[1][1]);
                mma16816(o[rt][3], ap, vf[1][2], vf[1][3]);
            }
        }
    }

    __syncthreads();
    if (tid < 64) stats[IX_CORR(tid)] = 1.0f / l_reg;
    __syncthreads();
    #pragma unroll
    for (int rt = 0; rt < 4; rt++) {
        int rA = rt * 16 + lq, rB = rA + 8;
        float ia = stats[IX_CORR(rA)];
        float ib = stats[IX_CORR(rB)];
        const size_t ra = (size_t)(qBase + rA) * CIN;
        const size_t rb = (size_t)(qBase + rB) * CIN;
        #pragma unroll
        for (int n = 0; n < 4; n++) {
            int c = chW + n * 8 + lc * 2;
            float2 r2 = *(const float2*)(resid + ra + c);
            *(float2*)(out + ra + c) =
                make_float2(fmaf(o[rt][n][0], ia, r2.x), fmaf(o[rt][n][1], ia, r2.y));
            float2 r3 = *(const float2*)(resid + rb + c);
            *(float2*)(out + rb + c) =
                make_float2(fmaf(o[rt][n][2], ib, r3.x), fmaf(o[rt][n][3], ib, r3.y));
        }
    }
}

extern "C" void kernel_launch(void* const* d_in, const int* in_sizes, int n_in,
                              void* d_out, int out_size) {
    const float* im1 = (const float*)d_in[0];
    const float* im2 = (const float*)d_in[1];
    const float* Wq  = (const float*)d_in[2];
    const float* Wk  = (const float*)d_in[3];
    const float* Wv  = (const float*)d_in[4];
    float* out = (float*)d_out;

    cudaFuncSetAttribute(attn_kernel, cudaFuncAttributeMaxDynamicSharedMemorySize, SM_TOTAL);

    dim3 pgrid(NTOK / 128, PCOLS / 64, 2);
    proj_kernel<<<pgrid, 256>>>(im1, im2, Wq, Wk, Wv);

    dim3 agrid(NTOK / BM, 2);
    attn_kernel<<<agrid, 512, SM_TOTAL>>>(im1, im2, out);
}

// round 15
// speedup vs baseline: 1.7370x; 1.7370x over previous
#include <cuda_runtime.h>
#include <cuda_fp16.h>
#include <cstdint>

#define NTOK 8192
#define CIN 512
#define DK 64
#define BM 64            // queries per CTA (attn)
#define BN 64            // keys per iteration
#define ITERS (NTOK / BN)
#define PCOLS 640

// ---------------- static scratch (fp16 operands) ----------------
__device__ __align__(16) __half g_qh[2][NTOK * DK];
__device__ __align__(16) __half g_ql[2][NTOK * DK];
__device__ __align__(16) __half g_kh[2][NTOK * DK];
__device__ __align__(16) __half g_kl[2][NTOK * DK];
__device__ __align__(16) __half g_vh[2][(size_t)NTOK * CIN];

// ---------------- PTX helpers (base ISA only) ----------------
__device__ __forceinline__ uint32_t smem_u32(const void* p) {
    uint32_t a;
    asm("{ .reg .u64 t; cvta.to.shared.u64 t, %1; cvt.u32.u64 %0, t; }" : "=r"(a) : "l"(p));
    return a;
}
__device__ __forceinline__ void mma16816(float* c, const uint32_t* a, uint32_t b0, uint32_t b1) {
    asm volatile(
        "mma.sync.aligned.m16n8k16.row.col.f32.f16.f16.f32 "
        "{%0,%1,%2,%3}, {%4,%5,%6,%7}, {%8,%9}, {%0,%1,%2,%3};"
        : "+f"(c[0]), "+f"(c[1]), "+f"(c[2]), "+f"(c[3])
        : "r"(a[0]), "r"(a[1]), "r"(a[2]), "r"(a[3]), "r"(b0), "r"(b1));
}
__device__ __forceinline__ void ldsm4(uint32_t* d, uint32_t addr) {
    asm volatile("ldmatrix.sync.aligned.m8n8.x4.shared.b16 {%0,%1,%2,%3}, [%4];"
                 : "=r"(d[0]), "=r"(d[1]), "=r"(d[2]), "=r"(d[3]) : "r"(addr));
}
__device__ __forceinline__ void ldsm4t(uint32_t* d, uint32_t addr) {
    asm volatile("ldmatrix.sync.aligned.m8n8.x4.trans.shared.b16 {%0,%1,%2,%3}, [%4];"
                 : "=r"(d[0]), "=r"(d[1]), "=r"(d[2]), "=r"(d[3]) : "r"(addr));
}
#define CP16(dst, src)  asm volatile("cp.async.cg.shared.global [%0], [%1], 16;" :: "r"(dst), "l"(src))
#define CPCOMMIT()      asm volatile("cp.async.commit_group;" ::: "memory")
#define CPWAIT0()       asm volatile("cp.async.wait_group 0;" ::: "memory")

// ---------------------------------------------------------------------------
// Kernel 1: HMMA QKV projection. V-CTAs use 2-term hi/lo (drop al*wh).
// ---------------------------------------------------------------------------
__global__ __launch_bounds__(256, 2)
void proj_kernel(const float* __restrict__ im1, const float* __restrict__ im2,
                 const float* __restrict__ Wq, const float* __restrict__ Wk,
                 const float* __restrict__ Wv) {
    const int img = blockIdx.z;
    const float* __restrict__ A = img ? im2 : im1;
    const int rowBase = blockIdx.x * 128;
    const int colBase = blockIdx.y * 64;
    const bool useAl = (colBase < 128);   // Q/K need full 3-term; V is 2-term

    __shared__ __align__(16) __half Ah[128 * 32];
    __shared__ __align__(16) __half Al[128 * 32];
    __shared__ __align__(16) __half Wh[32 * 64];
    __shared__ __align__(16) __half Wl[32 * 64];

    const int tid = threadIdx.x, warp = tid >> 5, lane = tid & 31;
    const int wr = warp & 3, wc = warp >> 2;
    const int l7 = lane & 7, l8 = (lane >> 3) & 1, l16 = lane >> 4;
    const int lq = lane >> 2, lc = lane & 3;
    const uint32_t sAh = smem_u32(Ah), sAl = smem_u32(Al);
    const uint32_t sWh = smem_u32(Wh), sWl = smem_u32(Wl);

    float o[2][4][4] = {};
    float4 aR[4];
    float4 wR[2];

    auto loadA = [&](int kt) {
        #pragma unroll
        for (int i = 0; i < 4; i++) {
            int idx = tid + i * 256;
            int r = idx >> 3, c4 = idx & 7;
            aR[i] = *(const float4*)(A + (size_t)(rowBase + r) * CIN + kt * 32 + c4 * 4);
        }
    };
    auto loadW = [&](int kt) {
        #pragma unroll
        for (int i = 0; i < 2; i++) {
            int idx = tid + i * 256;
            int r = idx >> 4, c4 = idx & 15;
            int krow = kt * 32 + r;
            int c = colBase + c4 * 4;
            const float* src;
            if (c < 64)       src = Wq + krow * DK + c;
            else if (c < 128) src = Wk + krow * DK + (c - 64);
            else              src = Wv + krow * CIN + (c - 128);
            wR[i] = *(const float4*)src;
        }
    };

    loadA(0); loadW(0);

    for (int kt = 0; kt < 16; kt++) {
        #pragma unroll
        for (int i = 0; i < 4; i++) {
            int idx = tid + i * 256;
            int r = idx >> 3, c4 = idx & 7;
            uint32_t off = (uint32_t)(r * 64 + (((c4 >> 1) ^ (r & 3)) * 16) + (c4 & 1) * 8);
            float4 v = aR[i];
            __half h0 = __float2half_rn(v.x), h1 = __float2half_rn(v.y);
            __half h2 = __float2half_rn(v.z), h3 = __float2half_rn(v.w);
            __half2 H0 = __halves2half2(h0, h1), H1 = __halves2half2(h2, h3);
            __half2 L0 = __halves2half2(__float2half_rn(v.x - __half2float(h0)),
                                        __float2half_rn(v.y - __half2float(h1)));
            __half2 L1 = __halves2half2(__float2half_rn(v.z - __half2float(h2)),
                                        __float2half_rn(v.w - __half2float(h3)));
            *(uint2*)((char*)Ah + off) = make_uint2(*(uint32_t*)&H0, *(uint32_t*)&H1);
            *(uint2*)((char*)Al + off) = make_uint2(*(uint32_t*)&L0, *(uint32_t*)&L1);
        }
        #pragma unroll
        for (int i = 0; i < 2; i++) {
            int idx = tid + i * 256;
            int r = idx >> 4, c4 = idx & 15;
            uint32_t off = (uint32_t)(r * 128 + (((c4 >> 1) ^ (r & 7)) * 16) + (c4 & 1) * 8);
            float4 v = wR[i];
            __half h0 = __float2half_rn(v.x), h1 = __float2half_rn(v.y);
            __half h2 = __float2half_rn(v.z), h3 = __float2half_rn(v.w);
            __half2 H0 = __halves2half2(h0, h1), H1 = __halves2half2(h2, h3);
            __half2 L0 = __halves2half2(__float2half_rn(v.x - __half2float(h0)),
                                        __float2half_rn(v.y - __half2float(h1)));
            __half2 L1 = __halves2half2(__float2half_rn(v.z - __half2float(h2)),
                                        __float2half_rn(v.w - __half2float(h3)));
            *(uint2*)((char*)Wh + off) = make_uint2(*(uint32_t*)&H0, *(uint32_t*)&H1);
            *(uint2*)((char*)Wl + off) = make_uint2(*(uint32_t*)&L0, *(uint32_t*)&L1);
        }
        __syncthreads();

        if (kt + 1 < 16) { loadA(kt + 1); loadW(kt + 1); }

        #pragma unroll
        for (int ks = 0; ks < 2; ks++) {
            uint32_t wh[2][4], wl[2][4];
            #pragma unroll
            for (int nt = 0; nt < 2; nt++) {
                int rr = ks * 16 + l7 + l8 * 8;
                uint32_t chunk = (uint32_t)((wc * 4 + nt * 2 + l16) ^ (rr & 7));
                ldsm4t(wh[nt], sWh + rr * 128 + chunk * 16);
                ldsm4t(wl[nt], sWl + rr * 128 + chunk * 16);
            }
            #pragma unroll
            for (int rt = 0; rt < 2; rt++) {
                int ar = wr * 32 + rt * 16 + l7 + l8 * 8;
                uint32_t ach = (uint32_t)((ks * 2 + l16) ^ (ar & 3));
                uint32_t ah[4], al[4];
                ldsm4(ah, sAh + ar * 64 + ach * 16);
                ldsm4(al, sAl + ar * 64 + ach * 16);
                #pragma unroll
                for (int nt = 0; nt < 2; nt++) {
                    mma16816(o[rt][nt * 2 + 0], ah, wh[nt][0], wh[nt][1]);
                    mma16816(o[rt][nt * 2 + 1], ah, wh[nt][2], wh[nt][3]);
                    mma16816(o[rt][nt * 2 + 0], ah, wl[nt][0], wl[nt][1]);
                    mma16816(o[rt][nt * 2 + 1], ah, wl[nt][2], wl[nt][3]);
                    if (useAl) {
                        mma16816(o[rt][nt * 2 + 0], al, wh[nt][0], wh[nt][1]);
                        mma16816(o[rt][nt * 2 + 1], al, wh[nt][2], wh[nt][3]);
                    }
                }
            }
        }
        __syncthreads();
    }

    #pragma unroll
    for (int rt = 0; rt < 2; rt++) {
        #pragma unroll
        for (int n = 0; n < 4; n++) {
            int rowA = rowBase + wr * 32 + rt * 16 + lq;
            int rowB = rowA + 8;
            int cA = wc * 32 + n * 8 + lc * 2;
            float v0 = o[rt][n][0], v1 = o[rt][n][1];
            float v2 = o[rt][n][2], v3 = o[rt][n][3];
            if (colBase == 0) {
                __half h0 = __float2half_rn(v0), h1 = __float2half_rn(v1);
                __half h2 = __float2half_rn(v2), h3 = __float2half_rn(v3);
                *(__half2*)&g_qh[img][rowA * DK + cA] = __halves2half2(h0, h1);
                *(__half2*)&g_qh[img][rowB * DK + cA] = __halves2half2(h2, h3);
                *(__half2*)&g_ql[img][rowA * DK + cA] =
                    __halves2half2(__float2half_rn(v0 - __half2float(h0)),
                                   __float2half_rn(v1 - __half2float(h1)));
                *(__half2*)&g_ql[img][rowB * DK + cA] =
                    __halves2half2(__float2half_rn(v2 - __half2float(h2)),
                                   __float2half_rn(v3 - __half2float(h3)));
            } else if (colBase == 64) {
                __half h0 = __float2half_rn(v0), h1 = __float2half_rn(v1);
                __half h2 = __float2half_rn(v2), h3 = __float2half_rn(v3);
                *(__half2*)&g_kh[img][rowA * DK + cA] = __halves2half2(h0, h1);
                *(__half2*)&g_kh[img][rowB * DK + cA] = __halves2half2(h2, h3);
                *(__half2*)&g_kl[img][rowA * DK + cA] =
                    __halves2half2(__float2half_rn(v0 - __half2float(h0)),
                                   __float2half_rn(v1 - __half2float(h1)));
                *(__half2*)&g_kl[img][rowB * DK + cA] =
                    __halves2half2(__float2half_rn(v2 - __half2float(h2)),
                                   __float2half_rn(v3 - __half2float(h3)));
            } else {
                int cv = colBase - 128 + cA;
                *(__half2*)&g_vh[img][(size_t)rowA * CIN + cv] =
                    __halves2half2(__float2half_rn(v0), __float2half_rn(v1));
                *(__half2*)&g_vh[img][(size_t)rowB * CIN + cv] =
                    __halves2half2(__float2half_rn(v2), __float2half_rn(v3));
            }
        }
    }
}

// ---------------- attn smem layout (BM=64, R11 structure) ----------------
#define IX_MROW(cur, row) ((cur) * 64 + (row))
#define IX_CORR(row)      (128 + (row))
#define IX_PMAX(g, row)   (192 + (g) * 64 + (row))
#define IX_PSUM(g, row)   (448 + (g) * 64 + (row))
#define SM_QH    3072
#define SM_QL    (SM_QH + 8192)
#define SM_KH(b) (19456 + (b) * 16384)
#define SM_KL(b) (27648 + (b) * 16384)
#define SM_V(b)  (52224 + (b) * 65536)
#define SM_P(b)  (183296 + (b) * 16384)
#define SM_TOTAL 216064

__device__ __forceinline__ void load_kv(uint32_t SB, const __half* Kh, const __half* Kl,
                                        const __half* Vh, int kb, int buf, int tid) {
    int r = tid >> 3, c = tid & 7;
    uint32_t sw = (uint32_t)((c ^ (r & 7)) * 16);
    CP16(SB + SM_KH(buf) + r * 128 + sw, Kh + (size_t)(kb + r) * DK + c * 8);
    CP16(SB + SM_KL(buf) + r * 128 + sw, Kl + (size_t)(kb + r) * DK + c * 8);
    #pragma unroll
    for (int i = 0; i < 8; i++) {
        int idx = tid + i * 512;
        int vr = idx >> 6, vc = idx & 63;
        CP16(SB + SM_V(buf) + vr * 1024 + (uint32_t)((vc ^ (vr & 7)) * 16),
             Vh + (size_t)(kb + vr) * CIN + vc * 8);
    }
}

// ---------------------------------------------------------------------------
// Kernel 2: HMMA flash attention, deferred PV (R11 structure, Q via ldsm).
// grid (128 qblocks, 2 sides), 512 threads, 2 barriers/iter.
// ---------------------------------------------------------------------------
__global__ __launch_bounds__(512, 1)
void attn_kernel(const float* __restrict__ im1, const float* __restrict__ im2,
                 float* __restrict__ out_all) {
    extern __shared__ char smem[];
    const uint32_t SB = smem_u32(smem);
    float* const stats = (float*)smem;

    const int tid  = threadIdx.x;
    const int warp = tid >> 5;
    const int lane = tid & 31;
    const int side  = blockIdx.y;
    const int qBase = blockIdx.x * BM;

    const __half* __restrict__ Qh = g_qh[side ^ 1];
    const __half* __restrict__ Ql = g_ql[side ^ 1];
    const __half* __restrict__ Kh = g_kh[side];
    const __half* __restrict__ Kl = g_kl[side];
    const __half* __restrict__ Vh = g_vh[side];
    const float* __restrict__ resid = side ? im2 : im1;
    float* __restrict__ out = out_all + (size_t)side * NTOK * CIN;

    const int rg = warp & 3;
    const int kg = warp >> 2;
    const int rows0 = rg * 16;
    const int key0  = kg * 16;
    const int chW   = warp * 32;

    const int l7  = lane & 7;
    const int l8  = (lane >> 3) & 1;
    const int l16 = lane >> 4;
    const int lq  = lane >> 2;
    const int lc  = lane & 3;
    const int row_a = rows0 + lq;
    const int row_b = row_a + 8;

    auto frag128 = [&](uint32_t base, int row0, int ks) -> uint32_t {
        int r  = row0 + l7 + l8 * 8;
        int ch = ks * 2 + l16;
        return SB + base + r * 128 + (uint32_t)(((ch ^ (r & 7)) & 7) * 16);
    };
    auto fragV = [&](int buf, int k0, int n0) -> uint32_t {
        int r  = k0 + l7 + l8 * 8;
        int ch = (n0 >> 3) + l16;
        return SB + SM_V(buf) + r * 1024 + (uint32_t)((ch ^ (r & 7)) * 16);
    };

    // ---- prologue: Q + K/V(0) ----
    if (tid < 64) stats[IX_MROW(0, tid)] = -1e30f;
    {
        int r = tid >> 3, c = tid & 7;
        uint32_t sw = (uint32_t)((c ^ (r & 7)) * 16);
        CP16(SB + SM_QH + r * 128 + sw, Qh + (size_t)(qBase + r) * DK + c * 8);
        CP16(SB + SM_QL + r * 128 + sw, Ql + (size_t)(qBase + r) * DK + c * 8);
        load_kv(SB, Kh, Kl, Vh, 0, 0, tid);
        CPCOMMIT();
    }
    CPWAIT0();
    __syncthreads();

    float o[4][4][4];
    #pragma unroll
    for (int rt = 0; rt < 4; rt++)
        #pragma unroll
        for (int n = 0; n < 4; n++)
            #pragma unroll
            for (int i = 0; i < 4; i++) o[rt][n][i] = 0.f;
    float l_reg = 0.f, corr_prev = 0.f;   // owner state (tid < 64)

    for (int it = 0; it < ITERS; it++) {
        const int b   = it & 1;
        const int bp  = b ^ 1;
        const int cur = it & 1, nxt = cur ^ 1;

        // ---------- Phase 1: QK(it) ----------
        float s[2][4];
        #pragma unroll
        for (int t = 0; t < 2; t++)
            #pragma unroll
            for (int i = 0; i < 4; i++) s[t][i] = 0.f;
        #pragma unroll
        for (int ks = 0; ks < 4; ks++) {
            uint32_t aqh[4], aql[4], bkh[4], bkl[4];
            ldsm4(aqh, frag128(SM_QH, rows0, ks));
            ldsm4(aql, frag128(SM_QL, rows0, ks));
            ldsm4(bkh, frag128(SM_KH(b), key0, ks));
            ldsm4(bkl, frag128(SM_KL(b), key0, ks));
            mma16816(s[0], aqh, bkh[0], bkh[2]);
            mma16816(s[1], aqh, bkh[1], bkh[3]);
            mma16816(s[0], aqh, bkl[0], bkl[2]);
            mma16816(s[1], aqh, bkl[1], bkl[3]);
            mma16816(s[0], aql, bkh[0], bkh[2]);
            mma16816(s[1], aql, bkh[1], bkh[3]);
        }

        // ---------- Phase 2: deferred PV(it-1) ----------
        if (it > 0) {
            if (tid < 64) {
                float ls = 0.f;
                #pragma unroll
                for (int g = 0; g < 4; g++) ls += stats[IX_PSUM(g, tid)];
                l_reg = l_reg * corr_prev + ls;
            }
            {
                float cr[4][2];
                bool allone = true;
                #pragma unroll
                for (int rt = 0; rt < 4; rt++) {
                    cr[rt][0] = stats[IX_CORR(rt * 16 + lq)];
                    cr[rt][1] = stats[IX_CORR(rt * 16 + lq + 8)];
                    allone = allone && (cr[rt][0] == 1.0f) && (cr[rt][1] == 1.0f);
                }
                if (!__all_sync(0xffffffffu, allone)) {
                    #pragma unroll
                    for (int rt = 0; rt < 4; rt++)
                        #pragma unroll
                        for (int n = 0; n < 4; n++) {
                            o[rt][n][0] *= cr[rt][0]; o[rt][n][1] *= cr[rt][0];
                            o[rt][n][2] *= cr[rt][1]; o[rt][n][3] *= cr[rt][1];
                        }
                }
            }
            #pragma unroll
            for (int ks = 0; ks < 4; ks++) {
                uint32_t vf[2][4];
                ldsm4t(vf[0], fragV(bp, ks * 16, chW + 0));
                ldsm4t(vf[1], fragV(bp, ks * 16, chW + 16));
                #pragma unroll
                for (int rt = 0; rt < 4; rt++) {
                    uint32_t ap[4];
                    ldsm4(ap, frag128(SM_P(bp), rt * 16, ks));
                    mma16816(o[rt][0], ap, vf[0][0], vf[0][1]);
                    mma16816(o[rt][1], ap, vf[0][2], vf[0][3]);
                    mma16816(o[rt][2], ap, vf[1][0], vf[1][1]);
                    mma16816(o[rt][3], ap, vf[1][2], vf[1][3]);
                }
            }
        }

        // ---------- Phase 3a: publish partial maxima ----------
        float ma = fmaxf(fmaxf(s[0][0], s[0][1]), fmaxf(s[1][0], s[1][1]));
        float mb = fmaxf(fmaxf(s[0][2], s[0][3]), fmaxf(s[1][2], s[1][3]));
        ma = fmaxf(ma, __shfl_xor_sync(0xffffffffu, ma, 1));
        ma = fmaxf(ma, __shfl_xor_sync(0xffffffffu, ma, 2));
        mb = fmaxf(mb, __shfl_xor_sync(0xffffffffu, mb, 1));
        mb = fmaxf(mb, __shfl_xor_sync(0xffffffffu, mb, 2));
        if (lc == 0) {
            stats[IX_PMAX(kg, row_a)] = ma;
            stats[IX_PMAX(kg, row_b)] = mb;
        }
        __syncthreads();                                   // barrier #1

        // ---------- Phase 3b: prefetch K/V(it+1) into freed buffer ----------
        if (it + 1 < ITERS) load_kv(SB, Kh, Kl, Vh, (it + 1) * BN, bp, tid);
        CPCOMMIT();

        // ---------- Phase 3c: combine, exp, write P(it), psums ----------
        if (tid < 64) {
            float mo = stats[IX_MROW(cur, tid)], mn = mo;
            #pragma unroll
            for (int g = 0; g < 4; g++) mn = fmaxf(mn, stats[IX_PMAX(g, tid)]);
            corr_prev = __expf(mo - mn);
            stats[IX_MROW(nxt, tid)] = mn;
            stats[IX_CORR(tid)] = corr_prev;
        }
        {
            float mA = stats[IX_MROW(cur, row_a)];
            float mB = stats[IX_MROW(cur, row_b)];
            #pragma unroll
            for (int g = 0; g < 4; g++) {
                mA = fmaxf(mA, stats[IX_PMAX(g, row_a)]);
                mB = fmaxf(mB, stats[IX_PMAX(g, row_b)]);
            }
            float la = 0.f, lb = 0.f;
            #pragma unroll
            for (int t = 0; t < 2; t++) {
                float p0 = __expf(s[t][0] - mA);
                float p1 = __expf(s[t][1] - mA);
                float p2 = __expf(s[t][2] - mB);
                float p3 = __expf(s[t][3] - mB);
                la += p0 + p1;
                lb += p2 + p3;
                __half2 hA = __floats2half2_rn(p0, p1);
                __half2 hB = __floats2half2_rn(p2, p3);
                int ch = kg * 2 + t;
                *(uint32_t*)(smem + SM_P(b) + row_a * 128 + ((ch ^ (row_a & 7)) * 16) + lc * 4) =
                    *(uint32_t*)&hA;
                *(uint32_t*)(smem + SM_P(b) + row_b * 128 + ((ch ^ (row_b & 7)) * 16) + lc * 4) =
                    *(uint32_t*)&hB;
            }
            la += __shfl_xor_sync(0xffffffffu, la, 1);
            la += __shfl_xor_sync(0xffffffffu, la, 2);
            lb += __shfl_xor_sync(0xffffffffu, lb, 1);
            lb += __shfl_xor_sync(0xffffffffu, lb, 2);
            if (lc == 0) {
                stats[IX_PSUM(kg, row_a)] = la;
                stats[IX_PSUM(kg, row_b)] = lb;
            }
        }
        CPWAIT0();
        __syncthreads();                                   // barrier #2
    }

    // ---------- epilogue: final PV(ITERS-1) ----------
    {
        const int bl = (ITERS - 1) & 1;
        if (tid < 64) {
            float ls = 0.f;
            #pragma unroll
            for (int g = 0; g < 4; g++) ls += stats[IX_PSUM(g, tid)];
            l_reg = l_reg * corr_prev + ls;
        }
        {
            float cr[4][2];
            bool allone = true;
            #pragma unroll
            for (int rt = 0; rt < 4; rt++) {
                cr[rt][0] = stats[IX_CORR(rt * 16 + lq)];
                cr[rt][1] = stats[IX_CORR(rt * 16 + lq + 8)];
                allone = allone && (cr[rt][0] == 1.0f) && (cr[rt][1] == 1.0f);
            }
            if (!__all_sync(0xffffffffu, allone)) {
                #pragma unroll
                for (int rt = 0; rt < 4; rt++)
                    #pragma unroll
                    for (int n = 0; n < 4; n++) {
                        o[rt][n][0] *= cr[rt][0]; o[rt][n][1] *= cr[rt][0];
                        o[rt][n][2] *= cr[rt][1]; o[rt][n][3] *= cr[rt][1];
                    }
            }
        }
        #pragma unroll
        for (int ks = 0; ks < 4; ks++) {
            uint32_t vf[2][4];
            ldsm4t(vf[0], fragV(bl, ks * 16, chW + 0));
            ldsm4t(vf[1], fragV(bl, ks * 16, chW + 16));
            #pragma unroll
            for (int rt = 0; rt < 4; rt++) {
                uint32_t ap[4];
                ldsm4(ap, frag128(SM_P(bl), rt * 16, ks));
                mma16816(o[rt][0], ap, vf[0][0], vf[0][1]);
                mma16816(o[rt][1], ap, vf[0][2], vf[0][3]);
                mma16816(o[rt][2], ap, vf[1][0], vf[1][1]);
                mma16816(o[rt][3], ap, vf[1][2], vf[1][3]);
            }
        }
    }

    __syncthreads();
    if (tid < 64) stats[IX_CORR(tid)] = 1.0f / l_reg;
    __syncthreads();
    #pragma unroll
    for (int rt = 0; rt < 4; rt++) {
        int rA = rt * 16 + lq, rB = rA + 8;
        float ia = stats[IX_CORR(rA)];
        float ib = stats[IX_CORR(rB)];
        const size_t ra = (size_t)(qBase + rA) * CIN;
        const size_t rb = (size_t)(qBase + rB) * CIN;
        #pragma unroll
        for (int n = 0; n < 4; n++) {
            int c = chW + n * 8 + lc * 2;
            float2 r2 = *(const float2*)(resid + ra + c);
            *(float2*)(out + ra + c) =
                make_float2(fmaf(o[rt][n][0], ia, r2.x), fmaf(o[rt][n][1], ia, r2.y));
            float2 r3 = *(const float2*)(resid + rb + c);
            *(float2*)(out + rb + c) =
                make_float2(fmaf(o[rt][n][2], ib, r3.x), fmaf(o[rt][n][3], ib, r3.y));
        }
    }
}

extern "C" void kernel_launch(void* const* d_in, const int* in_sizes, int n_in,
                              void* d_out, int out_size) {
    const float* im1 = (const float*)d_in[0];
    const float* im2 = (const float*)d_in[1];
    const float* Wq  = (const float*)d_in[2];
    const float* Wk  = (const float*)d_in[3];
    const float* Wv  = (const float*)d_in[4];
    float* out = (float*)d_out;

    cudaFuncSetAttribute(attn_kernel, cudaFuncAttributeMaxDynamicSharedMemorySize, SM_TOTAL);

    dim3 pgrid(NTOK / 128, PCOLS / 64, 2);
    proj_kernel<<<pgrid, 256>>>(im1, im2, Wq, Wk, Wv);

    dim3 agrid(NTOK / BM, 2);
    attn_kernel<<<agrid, 512, SM_TOTAL>>>(im1, im2, out);
}